// round 16
// baseline (speedup 1.0000x reference)
#include <cuda_runtime.h>
#include <cuda_fp16.h>
#include <cstdint>
#include <cstddef>

#define Bv     8
#define Nv     128
#define FNv    64

// fp16 B operand in global: [n=2l+br (128 rows)][kp (192 perm + pad16)] halves (208/row).
// ks 0..3 = We rows (W[128+k]), ks 4..7 = Wj rows (W[k]), ks 8..11 = Wi rows (W[k-128]).
__device__ unsigned short g_Wh[128 * 208];

// ------------------------------ helpers ------------------------------
__device__ __forceinline__ uint32_t smem_u32(const void* p) {
    uint32_t a;
    asm("{ .reg .u64 t; cvta.to.shared.u64 t, %1; cvt.u32.u64 %0, t; }" : "=r"(a) : "l"(p));
    return a;
}
__device__ __forceinline__ void cp16(uint32_t dst, const void* src) {
    asm volatile("cp.async.cg.shared.global [%0], [%1], 16;" :: "r"(dst), "l"(src) : "memory");
}
__device__ __forceinline__ void cp_commit() {
    asm volatile("cp.async.commit_group;" ::: "memory");
}
template <int N>
__device__ __forceinline__ void cp_wait() {
    asm volatile("cp.async.wait_group %0;" :: "n"(N) : "memory");
}
__device__ __forceinline__ uint32_t packh2(float lo, float hi) {
    uint32_t d; asm("cvt.rn.f16x2.f32 %0, %1, %2;" : "=r"(d) : "f"(hi), "f"(lo)); return d;
}
__device__ __forceinline__ void mma16(float* c, const uint32_t* a, uint32_t b0, uint32_t b1) {
    asm volatile(
        "mma.sync.aligned.m16n8k16.row.col.f32.f16.f16.f32 "
        "{%0,%1,%2,%3}, {%4,%5,%6,%7}, {%8,%9}, {%0,%1,%2,%3};"
        : "+f"(c[0]), "+f"(c[1]), "+f"(c[2]), "+f"(c[3])
        : "r"(a[0]), "r"(a[1]), "r"(a[2]), "r"(a[3]), "r"(b0), "r"(b1));
}
__device__ __forceinline__ double pack2d(float x, float y) {
    double r; asm("mov.b64 %0, {%1, %2};" : "=d"(r) : "f"(x), "f"(y)); return r;
}
__device__ __forceinline__ double add2(double a, double b) {
    double r; asm("add.rn.f32x2 %0, %1, %2;" : "=d"(r) : "d"(a), "d"(b)); return r;
}
__device__ __forceinline__ double fma2v(double a, double b, double c) {
    double r; asm("fma.rn.f32x2 %0, %1, %2, %3;" : "=d"(r) : "d"(a), "d"(b), "d"(c)); return r;
}
__device__ __forceinline__ float2 unpack2d(double v) {
    float2 f; asm("mov.b64 {%0, %1}, %2;" : "=f"(f.x), "=f"(f.y) : "d"(v)); return f;
}

// ------------------------------ weight prep (proven) ------------------------------
__global__ void __launch_bounds__(256)
wprep_kernel(const float* __restrict__ Watt, const float* __restrict__ Wnei) {
    const int idx = blockIdx.x * 256 + threadIdx.x;   // < 26624 = 104*256
    const int n = idx / 208, kp = idx % 208;
    const int l = n >> 1, br = n & 1;
    float val = 0.f;
    if (kp < 192) {
        const int ks = kp >> 4, p16 = kp & 15;
        const int k16 = ((p16 >> 2) * 2) + (p16 & 1) + ((p16 >> 1) & 1) * 8;
        const int kglob = ks * 16 + k16;
        int row;
        if (ks < 4)      row = 128 + kglob;
        else if (ks < 8) row = kglob;
        else             row = kglob - 128;
        const float* __restrict__ W = br ? Wnei : Watt;
        val = W[row * 64 + l];
    }
    g_Wh[idx] = __half_as_ushort(__float2half_rn(val));
}

// ------------------------------ main kernel ------------------------------
// CTA = (b, jb of 4 j's). grid 256, 256 threads, 2 CTAs/SM.
// Main tile: 64 rows (r = il*4 + jl; i = ii*16+il, j = jb*4+jl) x 128 n-cols.
// Warps: wm = wid&3 -> 16-row m-tile (main) / 32 rows (prologue); wn = wid>>2 -> 64 n-cols.
#define OFF_W   0            // 128 x 416 B = 53248
#define OFF_E16 53248        // 2 x 10240 = 20480 (H tile 128 rows spans both pre-loop)
#define E16BUF  10240
#define OFF_PI  73728        // 128 i x 66 uint32 (half2 + pad) = 33792
#define PIW32   66
#define OFF_PJ  107520       // 4 jl x 66 float2 = 2112
#define PJW     66
#define OFF_A   109632       // 128 i x 4 j fp32 = 2048
#define OFF_BS  111680       // 64 float2 (pre-halved) = 512
#define SMEM_DYN 112192

__global__ void __launch_bounds__(256, 2)
main_kernel(const float* __restrict__ A,
            const float* __restrict__ E,
            const float* __restrict__ H,
            const float* __restrict__ biasA,
            const float* __restrict__ biasN,
            float* __restrict__ out) {
    extern __shared__ char sm[];
    const uint32_t sb = smem_u32(sm);

    const int t = threadIdx.x, lane = t & 31, wid = t >> 5;
    const int g = lane >> 2, tg = lane & 3;
    const int b = blockIdx.x >> 5, jb = blockIdx.x & 31;
    const int wm = wid & 3, wn = wid >> 2;
    const int lbase = wn * 32;
    const int nrow0 = wn * 64;

    const uint32_t* __restrict__ Ws = (const uint32_t*)(sm + OFF_W);

    // ---- cp.async: W (from g_Wh) + A column-block ----
    {
        #pragma unroll
        for (int v = 0; v < 13; v++) {
            const int n = v * 256 + t;
            if (n < 3328) cp16(sb + OFF_W + n * 16, (const char*)g_Wh + n * 16);
        }
        if (t < 128)
            cp16(sb + OFF_A + t * 16,
                 (const char*)(A + ((size_t)(b * Nv + t)) * Nv + jb * 4));
        cp_commit();
    }

    // ---- H tile: LDG -> fp16 permuted STS spanning both E16 buffers ----
    {
        const float4* Hg = (const float4*)(H + (size_t)b * Nv * FNv);
        float4 hl[8];
        #pragma unroll
        for (int v = 0; v < 8; v++) hl[v] = Hg[v * 256 + t];
        uint32_t* Ebw = (uint32_t*)(sm + OFF_E16);
        #pragma unroll
        for (int v = 0; v < 8; v++) {
            const int n = v * 256 + t, row = n >> 4, kgf = n & 15;
            const int wbase = row * 40 + (kgf >> 2) * 8 + ((kgf & 1) * 4) + ((kgf >> 1) & 1);
            Ebw[wbase]     = packh2(hl[v].x, hl[v].y);
            Ebw[wbase + 2] = packh2(hl[v].z, hl[v].w);
        }
    }
    if (t < 64)
        ((float2*)(sm + OFF_BS))[t] =
            make_float2(0.5f * __ldg(biasA + t), 0.5f * __ldg(biasN + t));
    cp_wait<0>();
    __syncthreads();          // W + A + H-tile resident

    const uint32_t* __restrict__ Hw = (const uint32_t*)(sm + OFF_E16);

    // ---- prologue pass 1: Pi (ks 8..11), M=128, store fp16 half2 ----
    {
        float cpi[2][8][4];
        #pragma unroll
        for (int mt = 0; mt < 2; mt++)
            #pragma unroll
            for (int nt = 0; nt < 8; nt++)
                #pragma unroll
                for (int q = 0; q < 4; q++) cpi[mt][nt][q] = 0.f;

        #pragma unroll
        for (int ks = 0; ks < 4; ks++) {
            uint32_t a[2][4];
            #pragma unroll
            for (int mt = 0; mt < 2; mt++) {
                const int r = wm * 32 + mt * 16 + g;
                const uint2 u0 = *(const uint2*)(Hw + r * 40 + ks * 8 + tg * 2);
                const uint2 u1 = *(const uint2*)(Hw + (r + 8) * 40 + ks * 8 + tg * 2);
                a[mt][0] = u0.x; a[mt][1] = u1.x; a[mt][2] = u0.y; a[mt][3] = u1.y;
            }
            #pragma unroll
            for (int nt = 0; nt < 8; nt++) {
                const uint2 bi = *(const uint2*)(Ws + (nrow0 + nt * 8 + g) * 104
                                                 + (ks + 8) * 8 + tg * 2);
                mma16(cpi[0][nt], a[0], bi.x, bi.y);
                mma16(cpi[1][nt], a[1], bi.x, bi.y);
            }
        }
        uint32_t* __restrict__ PIh = (uint32_t*)(sm + OFF_PI);
        #pragma unroll
        for (int mt = 0; mt < 2; mt++) {
            const int r0 = wm * 32 + mt * 16 + g;
            #pragma unroll
            for (int nt = 0; nt < 8; nt++) {
                const int l = lbase + nt * 4 + tg;
                PIh[r0 * PIW32 + l]       = packh2(cpi[mt][nt][0], cpi[mt][nt][1]);
                PIh[(r0 + 8) * PIW32 + l] = packh2(cpi[mt][nt][2], cpi[mt][nt][3]);
            }
        }
    }
    // ---- prologue pass 2: Pj (ks 4..7), keep only window rows jb*4..+4 ----
    {
        float cpj[2][8][4];
        #pragma unroll
        for (int mt = 0; mt < 2; mt++)
            #pragma unroll
            for (int nt = 0; nt < 8; nt++)
                #pragma unroll
                for (int q = 0; q < 4; q++) cpj[mt][nt][q] = 0.f;

        #pragma unroll
        for (int ks = 0; ks < 4; ks++) {
            uint32_t a[2][4];
            #pragma unroll
            for (int mt = 0; mt < 2; mt++) {
                const int r = wm * 32 + mt * 16 + g;
                const uint2 u0 = *(const uint2*)(Hw + r * 40 + ks * 8 + tg * 2);
                const uint2 u1 = *(const uint2*)(Hw + (r + 8) * 40 + ks * 8 + tg * 2);
                a[mt][0] = u0.x; a[mt][1] = u1.x; a[mt][2] = u0.y; a[mt][3] = u1.y;
            }
            #pragma unroll
            for (int nt = 0; nt < 8; nt++) {
                const uint2 bj = *(const uint2*)(Ws + (nrow0 + nt * 8 + g) * 104
                                                 + (ks + 4) * 8 + tg * 2);
                mma16(cpj[0][nt], a[0], bj.x, bj.y);
                mma16(cpj[1][nt], a[1], bj.x, bj.y);
            }
        }
        float2* __restrict__ PJs = (float2*)(sm + OFF_PJ);
        #pragma unroll
        for (int mt = 0; mt < 2; mt++) {
            #pragma unroll
            for (int h = 0; h < 2; h++) {
                const int row = wm * 32 + mt * 16 + h * 8 + g;   // node index
                if ((row >> 2) == jb) {
                    #pragma unroll
                    for (int nt = 0; nt < 8; nt++) {
                        const int l = lbase + nt * 4 + tg;
                        PJs[(size_t)(row & 3) * PJW + l] =
                            make_float2(cpj[mt][nt][h * 2], cpj[mt][nt][h * 2 + 1]);
                    }
                }
            }
        }
    }

    // ---- prefetch E tile 0 (64 rows: r = il*4+jl) ----
    float4 el[4];
    {
        #pragma unroll
        for (int v = 0; v < 4; v++) {
            const int n = v * 256 + t, row = n >> 4, kgf = n & 15;
            el[v] = __ldg((const float4*)
                (E + (((size_t)(b * Nv + (row >> 2)) * Nv) + jb * 4 + (row & 3)) * FNv) + kgf);
        }
    }
    __syncthreads();          // Pi/Pj visible; H reads done -> bufs reusable

    float outacc[8];
    #pragma unroll
    for (int nt = 0; nt < 8; nt++) outacc[nt] = 0.f;

    for (int ii = 0; ii < 8; ii++) {
        // ---- convert + store tile ii (64 rows) ----
        {
            uint32_t* Ebw = (uint32_t*)(sm + OFF_E16 + (ii & 1) * E16BUF);
            #pragma unroll
            for (int v = 0; v < 4; v++) {
                const int n = v * 256 + t, row = n >> 4, kgf = n & 15;
                const int wbase = row * 40 + (kgf >> 2) * 8 + ((kgf & 1) * 4) + ((kgf >> 1) & 1);
                Ebw[wbase]     = packh2(el[v].x, el[v].y);
                Ebw[wbase + 2] = packh2(el[v].z, el[v].w);
            }
        }
        __syncthreads();

        // ---- prefetch tile ii+1 ----
        if (ii + 1 < 8) {
            #pragma unroll
            for (int v = 0; v < 4; v++) {
                const int n = v * 256 + t, row = n >> 4, kgf = n & 15;
                el[v] = __ldg((const float4*)
                    (E + (((size_t)(b * Nv + (ii + 1) * 16 + (row >> 2)) * Nv)
                          + jb * 4 + (row & 3)) * FNv) + kgf);
            }
        }

        // ---- GEMM: M=64, warp m-tile rows wm*16..+16; B from smem ----
        const uint32_t* __restrict__ Ew = (const uint32_t*)(sm + OFF_E16 + (ii & 1) * E16BUF);
        float c[8][4];
        #pragma unroll
        for (int nt = 0; nt < 8; nt++)
            #pragma unroll
            for (int q = 0; q < 4; q++) c[nt][q] = 0.f;

        #pragma unroll
        for (int ks = 0; ks < 4; ks++) {
            uint32_t a[4];
            const int r = wm * 16 + g;
            const uint2 u0 = *(const uint2*)(Ew + r * 40 + ks * 8 + tg * 2);
            const uint2 u1 = *(const uint2*)(Ew + (r + 8) * 40 + ks * 8 + tg * 2);
            a[0] = u0.x; a[1] = u1.x; a[2] = u0.y; a[3] = u1.y;
            #pragma unroll
            for (int nt = 0; nt < 8; nt++) {
                const uint2 bu = *(const uint2*)(Ws + (nrow0 + nt * 8 + g) * 104
                                                 + ks * 8 + tg * 2);
                mma16(c[nt], a, bu.x, bu.y);
            }
        }

        // ---- epilogue: gate + i-accumulate (j = jb*4 + (g&3) per thread) ----
        const float*    __restrict__ As  = (const float*)(sm + OFF_A);
        const uint32_t* __restrict__ PIh = (const uint32_t*)(sm + OFF_PI);
        const double*   __restrict__ PJd = (const double*)(sm + OFF_PJ);
        const double*   __restrict__ Bsd = (const double*)(sm + OFF_BS);

        const int i0 = ii * 16 + wm * 4 + (g >> 2);      // h=0 row; h=1 -> i0+2
        const float ah0 = 0.5f * As[i0 * 4 + (g & 3)];
        const float ah1 = 0.5f * As[(i0 + 2) * 4 + (g & 3)];
        const double a20 = pack2d(ah0, ah0);
        const double a21 = pack2d(ah1, ah1);

        #pragma unroll
        for (int nt = 0; nt < 8; nt++) {
            const int l = lbase + nt * 4 + tg;
            const double pj = PJd[(size_t)(g & 3) * PJW + l];
            const double bs = Bsd[l];
            {
                const uint32_t piu = PIh[i0 * PIW32 + l];
                const float2 pif = __half22float2(*reinterpret_cast<const half2*>(&piu));
                const double s2 = add2(add2(pack2d(c[nt][0], c[nt][1]),
                                            pack2d(pif.x, pif.y)), pj);
                const float2 r = unpack2d(fma2v(a20, s2, bs));
                float th; asm("tanh.approx.f32 %0, %1;" : "=f"(th) : "f"(r.x));
                outacc[nt] = fmaf(fmaxf(r.y, 0.f), fmaf(0.5f, th, 0.5f), outacc[nt]);
            }
            {
                const uint32_t piu = PIh[(i0 + 2) * PIW32 + l];
                const float2 pif = __half22float2(*reinterpret_cast<const half2*>(&piu));
                const double s2 = add2(add2(pack2d(c[nt][2], c[nt][3]),
                                            pack2d(pif.x, pif.y)), pj);
                const float2 r = unpack2d(fma2v(a21, s2, bs));
                float th; asm("tanh.approx.f32 %0, %1;" : "=f"(th) : "f"(r.x));
                outacc[nt] = fmaf(fmaxf(r.y, 0.f), fmaf(0.5f, th, 0.5f), outacc[nt]);
            }
        }
    }

    // ---- cross-warp reduction (8 partials per (j,l)) + store ----
    __syncthreads();
    float* __restrict__ Sred = (float*)(sm + OFF_E16);   // 8 planes x 256 floats
    #pragma unroll
    for (int nt = 0; nt < 8; nt++)
        Sred[(wm * 2 + (g >> 2)) * 256 + (g & 3) * 64 + lbase + nt * 4 + tg] = outacc[nt];
    __syncthreads();

    {
        float s = 0.f;
        #pragma unroll
        for (int w = 0; w < 8; w++) s += Sred[w * 256 + t];
        out[((size_t)(b * Nv) + jb * 4 + (t >> 6)) * FNv + (t & 63)] = 2.f * s;
    }
}

// ------------------------------ launch ------------------------------
extern "C" void kernel_launch(void* const* d_in, const int* in_sizes, int n_in,
                              void* d_out, int out_size) {
    const float* H    = (const float*)d_in[0];
    const float* A    = (const float*)d_in[1];
    const float* E    = (const float*)d_in[2];
    const float* Watt = (const float*)d_in[3];
    const float* Wnei = (const float*)d_in[4];
    const float* bAtt = (const float*)d_in[5];
    const float* bNei = (const float*)d_in[6];
    float* out = (float*)d_out;

    cudaFuncSetAttribute(main_kernel, cudaFuncAttributeMaxDynamicSharedMemorySize, SMEM_DYN);

    wprep_kernel<<<104, 256>>>(Watt, Wnei);
    main_kernel<<<Bv * 32, 256, SMEM_DYN>>>(A, E, H, bAtt, bNei, out);
}

// round 17
// speedup vs baseline: 1.4949x; 1.4949x over previous
#include <cuda_runtime.h>
#include <cuda_fp16.h>
#include <cstdint>
#include <cstddef>

#define Bv     8
#define Nv     128
#define FNv    64

// ------------------------------ device scratch ------------------------------
// g_Wh: fp16 We-only B operand [n=2l+br (128 rows)][kp (64 perm + pad8)] halves (72/row).
__device__ unsigned short g_Wh[128 * 72];
__device__ uint32_t g_Pih[Bv * Nv * FNv];   // half2 (att,nei), H@Wi
__device__ float2   g_Pjf[Bv * Nv * FNv];   // fp32  (att,nei), H@Wj

// ------------------------------ helpers ------------------------------
__device__ __forceinline__ uint32_t smem_u32(const void* p) {
    uint32_t a;
    asm("{ .reg .u64 t; cvta.to.shared.u64 t, %1; cvt.u32.u64 %0, t; }" : "=r"(a) : "l"(p));
    return a;
}
__device__ __forceinline__ void cp16(uint32_t dst, const void* src) {
    asm volatile("cp.async.cg.shared.global [%0], [%1], 16;" :: "r"(dst), "l"(src) : "memory");
}
__device__ __forceinline__ void cp_commit() {
    asm volatile("cp.async.commit_group;" ::: "memory");
}
template <int N>
__device__ __forceinline__ void cp_wait() {
    asm volatile("cp.async.wait_group %0;" :: "n"(N) : "memory");
}
__device__ __forceinline__ uint32_t packh2(float lo, float hi) {
    uint32_t d; asm("cvt.rn.f16x2.f32 %0, %1, %2;" : "=r"(d) : "f"(hi), "f"(lo)); return d;
}
__device__ __forceinline__ void mma16(float* c, const uint32_t* a, uint32_t b0, uint32_t b1) {
    asm volatile(
        "mma.sync.aligned.m16n8k16.row.col.f32.f16.f16.f32 "
        "{%0,%1,%2,%3}, {%4,%5,%6,%7}, {%8,%9}, {%0,%1,%2,%3};"
        : "+f"(c[0]), "+f"(c[1]), "+f"(c[2]), "+f"(c[3])
        : "r"(a[0]), "r"(a[1]), "r"(a[2]), "r"(a[3]), "r"(b0), "r"(b1));
}
__device__ __forceinline__ double pack2d(float x, float y) {
    double r; asm("mov.b64 %0, {%1, %2};" : "=d"(r) : "f"(x), "f"(y)); return r;
}
__device__ __forceinline__ double add2(double a, double b) {
    double r; asm("add.rn.f32x2 %0, %1, %2;" : "=d"(r) : "d"(a), "d"(b)); return r;
}
__device__ __forceinline__ double fma2v(double a, double b, double c) {
    double r; asm("fma.rn.f32x2 %0, %1, %2, %3;" : "=d"(r) : "d"(a), "d"(b), "d"(c)); return r;
}
__device__ __forceinline__ float2 unpack2d(double v) {
    float2 f; asm("mov.b64 {%0, %1}, %2;" : "=f"(f.x), "=f"(f.y) : "d"(v)); return f;
}

// ------------------------------ prep kernel ------------------------------
// blocks [0,256): node projections, 4 nodes/block.
// blocks [256,292): g_Wh We slice (proven permutation, ks<4).
__global__ void __launch_bounds__(256)
prep2_kernel(const float* __restrict__ H,
             const float* __restrict__ Watt,
             const float* __restrict__ Wnei) {
    const int t = threadIdx.x;
    if (blockIdx.x < 256) {
        const int bn0 = blockIdx.x * 4;
        __shared__ float Hs[4][64];
        Hs[t >> 6][t & 63] = H[bn0 * 64 + t];
        __syncthreads();

        const int l = t & 63;
        const int nh = (t >> 6) & 1;          // node pair selector
        const int part = t >> 7;              // 0 = Wi rows, 1 = Wj rows
        const int ro = part * 64;
        float aA[2] = {0.f, 0.f}, aN[2] = {0.f, 0.f};
        #pragma unroll 8
        for (int f = 0; f < 64; f++) {
            const float wa = __ldg(Watt + (ro + f) * 64 + l);
            const float wq = __ldg(Wnei + (ro + f) * 64 + l);
            #pragma unroll
            for (int k = 0; k < 2; k++) {
                const float h = Hs[nh * 2 + k][f];
                aA[k] = fmaf(h, wa, aA[k]);
                aN[k] = fmaf(h, wq, aN[k]);
            }
        }
        #pragma unroll
        for (int k = 0; k < 2; k++) {
            const int node = bn0 + nh * 2 + k;
            if (part == 0) g_Pih[node * 64 + l] = packh2(aA[k], aN[k]);
            else           g_Pjf[node * 64 + l] = make_float2(aA[k], aN[k]);
        }
    } else {
        const int idx = (blockIdx.x - 256) * 256 + t;     // < 9216 = 128*72
        if (idx < 9216) {
            const int n = idx / 72, kp = idx % 72;
            const int l = n >> 1, br = n & 1;
            float val = 0.f;
            if (kp < 64) {
                const int ks = kp >> 4, p16 = kp & 15;
                const int k16 = ((p16 >> 2) * 2) + (p16 & 1) + ((p16 >> 1) & 1) * 8;
                const int row = 128 + ks * 16 + k16;      // We rows
                const float* __restrict__ W = br ? Wnei : Watt;
                val = W[row * 64 + l];
            }
            g_Wh[idx] = __half_as_ushort(__float2half_rn(val));
        }
    }
}

// ------------------------------ main kernel ------------------------------
// CTA = (b, jb of 4 j's). grid 256, 256 threads, 2 CTAs/SM.
// Tile: 64 rows (r = il*4 + jl; i = ii*16+il, j = jb*4+jl) x 128 n-cols.
// Warps: wm = wid&1 -> rows [wm*32, +32) (mt 0..1 of 16); wn = wid>>1 -> 32 n-cols (16 l).
#define WROWW   36           // W row stride in words (72 halves)
#define OFF_W   0            // 128 x 144 B = 18432
#define OFF_E16 18432        // 2 x 10240 = 20480
#define E16BUF  10240
#define OFF_PI  38912        // 128 i x 68 uint32 (half2 + pad) = 34816
#define PIW32   68
#define OFF_PJ  73728        // 4 jl x 66 float2 = 2112 (+pad)
#define PJW     66
#define OFF_A   75840        // 128 i x 4 j fp32 = 2048
#define OFF_BS  77888        // 64 float2 (pre-halved) = 512
#define SMEM_DYN 78400

__global__ void __launch_bounds__(256, 2)
main_kernel(const float* __restrict__ A,
            const float* __restrict__ E,
            const float* __restrict__ biasA,
            const float* __restrict__ biasN,
            float* __restrict__ out) {
    extern __shared__ char sm[];
    const uint32_t sb = smem_u32(sm);

    const int t = threadIdx.x, lane = t & 31, wid = t >> 5;
    const int g = lane >> 2, tg = lane & 3;
    const int b = blockIdx.x >> 5, jb = blockIdx.x & 31;
    const int wm = wid & 1, wn = wid >> 1;

    const uint32_t* __restrict__ Ws = (const uint32_t*)(sm + OFF_W);

    // ---- cp.async: W + A ----
    {
        #pragma unroll
        for (int v = 0; v < 5; v++) {
            const int n = v * 256 + t;
            if (n < 1152) cp16(sb + OFF_W + n * 16, (const char*)g_Wh + n * 16);
        }
        if (t < 128)
            cp16(sb + OFF_A + t * 16,
                 (const char*)(A + ((size_t)(b * Nv + t)) * Nv + jb * 4));
        cp_commit();
    }
    // ---- PI: LDG.128 -> STS (padded rows) ----
    {
        uint32_t* __restrict__ PIh = (uint32_t*)(sm + OFF_PI);
        #pragma unroll
        for (int v = 0; v < 8; v++) {
            const int idx4 = v * 256 + t;           // 2048 = 128 i x 16 l4-groups
            const int i = idx4 >> 4, l4 = (idx4 & 15) * 4;
            const uint4 u = __ldg((const uint4*)(g_Pih + ((size_t)(b * Nv) + i) * 64 + l4));
            *(uint4*)(PIh + i * PIW32 + l4) = u;
        }
    }
    // ---- PJ window + bias ----
    {
        const int jl = t >> 6, l = t & 63;
        ((float2*)(sm + OFF_PJ))[jl * PJW + l] =
            __ldg(g_Pjf + ((size_t)(b * Nv) + jb * 4 + jl) * 64 + l);
    }
    if (t < 64)
        ((float2*)(sm + OFF_BS))[t] =
            make_float2(0.5f * __ldg(biasA + t), 0.5f * __ldg(biasN + t));

    // ---- prefetch E tile 0 (64 rows: r = il*4+jl) ----
    float4 el[4];
    {
        #pragma unroll
        for (int v = 0; v < 4; v++) {
            const int n = v * 256 + t, row = n >> 4, kgf = n & 15;
            el[v] = __ldg((const float4*)
                (E + (((size_t)(b * Nv + (row >> 2)) * Nv) + jb * 4 + (row & 3)) * FNv) + kgf);
        }
    }
    cp_wait<0>();
    __syncthreads();          // W + A + PI + PJ + BS resident

    // ---- hoist B fragments (We) into registers ----
    uint2 Breg[4][4];
    #pragma unroll
    for (int ks = 0; ks < 4; ks++)
        #pragma unroll
        for (int nt = 0; nt < 4; nt++)
            Breg[ks][nt] = *(const uint2*)(Ws + (wn * 32 + nt * 8 + g) * WROWW
                                           + ks * 8 + tg * 2);

    float outacc[4];
    #pragma unroll
    for (int nt = 0; nt < 4; nt++) outacc[nt] = 0.f;

    for (int ii = 0; ii < 8; ii++) {
        // ---- convert + store tile ii ----
        {
            uint32_t* Ebw = (uint32_t*)(sm + OFF_E16 + (ii & 1) * E16BUF);
            #pragma unroll
            for (int v = 0; v < 4; v++) {
                const int n = v * 256 + t, row = n >> 4, kgf = n & 15;
                const int wbase = row * 40 + (kgf >> 2) * 8 + ((kgf & 1) * 4) + ((kgf >> 1) & 1);
                Ebw[wbase]     = packh2(el[v].x, el[v].y);
                Ebw[wbase + 2] = packh2(el[v].z, el[v].w);
            }
        }
        __syncthreads();

        // ---- prefetch tile ii+1 ----
        if (ii + 1 < 8) {
            #pragma unroll
            for (int v = 0; v < 4; v++) {
                const int n = v * 256 + t, row = n >> 4, kgf = n & 15;
                el[v] = __ldg((const float4*)
                    (E + (((size_t)(b * Nv + (ii + 1) * 16 + (row >> 2)) * Nv)
                          + jb * 4 + (row & 3)) * FNv) + kgf);
            }
        }

        // ---- GEMM: warp rows [wm*32, +32), n-cols [wn*32, +32), B in regs ----
        const uint32_t* __restrict__ Ew = (const uint32_t*)(sm + OFF_E16 + (ii & 1) * E16BUF);
        float c[2][4][4];
        #pragma unroll
        for (int mt = 0; mt < 2; mt++)
            #pragma unroll
            for (int nt = 0; nt < 4; nt++)
                #pragma unroll
                for (int q = 0; q < 4; q++) c[mt][nt][q] = 0.f;

        #pragma unroll
        for (int ks = 0; ks < 4; ks++) {
            uint32_t a[2][4];
            #pragma unroll
            for (int mt = 0; mt < 2; mt++) {
                const int r = wm * 32 + mt * 16 + g;
                const uint2 u0 = *(const uint2*)(Ew + r * 40 + ks * 8 + tg * 2);
                const uint2 u1 = *(const uint2*)(Ew + (r + 8) * 40 + ks * 8 + tg * 2);
                a[mt][0] = u0.x; a[mt][1] = u1.x; a[mt][2] = u0.y; a[mt][3] = u1.y;
            }
            #pragma unroll
            for (int nt = 0; nt < 4; nt++) {
                mma16(c[0][nt], a[0], Breg[ks][nt].x, Breg[ks][nt].y);
                mma16(c[1][nt], a[1], Breg[ks][nt].x, Breg[ks][nt].y);
            }
        }

        // ---- epilogue: gate + i-accumulate (j = jb*4 + (g&3) fixed per thread) ----
        const float*    __restrict__ As  = (const float*)(sm + OFF_A);
        const uint32_t* __restrict__ PIh = (const uint32_t*)(sm + OFF_PI);
        const double*   __restrict__ PJd = (const double*)(sm + OFF_PJ);
        const double*   __restrict__ Bsd = (const double*)(sm + OFF_BS);

        #pragma unroll
        for (int mt = 0; mt < 2; mt++) {
            #pragma unroll
            for (int h = 0; h < 2; h++) {
                const int i0 = ii * 16 + wm * 8 + mt * 4 + h * 2 + (g >> 2);
                const float ah = 0.5f * As[i0 * 4 + (g & 3)];
                const double a2 = pack2d(ah, ah);
                #pragma unroll
                for (int nt = 0; nt < 4; nt++) {
                    const int l = wn * 16 + nt * 4 + tg;
                    const uint32_t piu = PIh[i0 * PIW32 + l];
                    const float2 pif = __half22float2(*reinterpret_cast<const half2*>(&piu));
                    const double s2 = add2(add2(pack2d(c[mt][nt][h * 2], c[mt][nt][h * 2 + 1]),
                                                pack2d(pif.x, pif.y)),
                                           PJd[(size_t)(g & 3) * PJW + l]);
                    const float2 r = unpack2d(fma2v(a2, s2, Bsd[l]));
                    float th; asm("tanh.approx.f32 %0, %1;" : "=f"(th) : "f"(r.x));
                    outacc[nt] = fmaf(fmaxf(r.y, 0.f), fmaf(0.5f, th, 0.5f), outacc[nt]);
                }
            }
        }
    }

    // ---- cross-warp reduction (4 partials per (j,l)) + store ----
    __syncthreads();
    float* __restrict__ Sred = (float*)(sm + OFF_E16);   // 4 planes x 256 floats
    #pragma unroll
    for (int nt = 0; nt < 4; nt++)
        Sred[(wm * 2 + (g >> 2)) * 256 + (g & 3) * 64 + wn * 16 + nt * 4 + tg] = outacc[nt];
    __syncthreads();

    {
        float s = 0.f;
        #pragma unroll
        for (int w = 0; w < 4; w++) s += Sred[w * 256 + t];
        out[((size_t)(b * Nv) + jb * 4 + (t >> 6)) * FNv + (t & 63)] = 2.f * s;
    }
}

// ------------------------------ launch ------------------------------
extern "C" void kernel_launch(void* const* d_in, const int* in_sizes, int n_in,
                              void* d_out, int out_size) {
    const float* H    = (const float*)d_in[0];
    const float* A    = (const float*)d_in[1];
    const float* E    = (const float*)d_in[2];
    const float* Watt = (const float*)d_in[3];
    const float* Wnei = (const float*)d_in[4];
    const float* bAtt = (const float*)d_in[5];
    const float* bNei = (const float*)d_in[6];
    float* out = (float*)d_out;

    cudaFuncSetAttribute(main_kernel, cudaFuncAttributeMaxDynamicSharedMemorySize, SMEM_DYN);

    prep2_kernel<<<292, 256>>>(H, Watt, Wnei);
    main_kernel<<<Bv * 32, 256, SMEM_DYN>>>(A, E, bAtt, bNei, out);
}